// round 12
// baseline (speedup 1.0000x reference)
#include <cuda_runtime.h>
#include <cuda_pipeline.h>

// Depthwise Conv1d: B=32, C=128, L=8192, kernel=3, stride=1, pad=1, fp32.
// out[b,c,l] = w[c,0]*x[b,c,l-1] + w[c,1]*x[b,c,l] + w[c,2]*x[b,c,l+1] + bias[c]
//
// R11 (= R10 resubmitted after infra failure): cp.async smem kernel with
// 16KB tiles for FULL occupancy. Each block handles half a row (1024 float4
// -> 16.4KB smem), so residency is warp-limited at 8 blocks/SM (64 warps,
// 100% theoretical occupancy) instead of smem-limited. 4 cp.async(16B) per
// thread = high in-flight DRAM bytes with ~28 regs. Halos are smem pads:
// tile-interior halos come from the tile itself; the two tile-edge elements
// are fetched by two threads via scalar LDG (L2 hits from neighbor tiles).

#define LEN    8192
#define LEN4   (LEN / 4)        // 2048 float4 per row
#define CHANS  128
#define ROWS   4096
#define NTHREADS 256
#define TILE4  1024             // float4 per block (half a row)
#define TILES_PER_ROW (LEN4 / TILE4)  // 2
#define NBLOCKS (ROWS * TILES_PER_ROW) // 8192
#define PER_THREAD (TILE4 / NTHREADS)  // 4

__global__ __launch_bounds__(NTHREADS)
void dwconv1d_kernel(const float* __restrict__ x,
                     const float* __restrict__ w,
                     const float* __restrict__ bias,
                     float* __restrict__ out)
{
    // s[4 .. 4+4096) = tile data; s[3] = left halo, s[4+4096] = right halo.
    __shared__ __align__(16) float s[4 * TILE4 + 8];

    const unsigned int blk  = blockIdx.x;
    const unsigned int row  = blk >> 1;             // / TILES_PER_ROW
    const unsigned int tile = blk & 1;              // 0 or 1 within row
    const unsigned int c    = row & (CHANS - 1);
    const unsigned int tid  = threadIdx.x;

    const float4* xt = reinterpret_cast<const float4*>(x)
                     + (size_t)row * LEN4 + (size_t)tile * TILE4;

    // ---- async load of the tile: 4 x 16B per thread, coalesced ----
#pragma unroll
    for (int k = 0; k < PER_THREAD; k++) {
        unsigned int p = tid + k * NTHREADS;
        __pipeline_memcpy_async(&s[4 + 4 * p], &xt[p], 16);
    }
    __pipeline_commit();

    // ---- tile-edge halos (2 scalar loads per block, L2 hits) ----
    const float* xe = reinterpret_cast<const float*>(xt);
    if (tid == 0)
        s[3] = (tile == 0) ? 0.0f : __ldg(xe - 1);
    else if (tid == 1)
        s[4 + 4 * TILE4] = (tile == TILES_PER_ROW - 1) ? 0.0f
                                                       : __ldg(xe + 4 * TILE4);

    // Per-channel taps (uniform across block -> broadcast)
    const float w0 = __ldg(&w[c * 3 + 0]);
    const float w1 = __ldg(&w[c * 3 + 1]);
    const float w2 = __ldg(&w[c * 3 + 2]);
    const float bb = __ldg(&bias[c]);

    __pipeline_wait_prior(0);
    __syncthreads();

    // ---- compute from smem + coalesced stores ----
    float4* ot = reinterpret_cast<float4*>(out)
               + (size_t)row * LEN4 + (size_t)tile * TILE4;

#pragma unroll
    for (int k = 0; k < PER_THREAD; k++) {
        unsigned int p = tid + k * NTHREADS;
        const float* sp = &s[4 * p];     // sp[3]=left, sp[4..7]=v, sp[8]=right
        float  l = sp[3];
        float4 v = *reinterpret_cast<const float4*>(sp + 4);
        float  r = sp[8];

        float4 o;
        o.x = fmaf(w0, l,   fmaf(w1, v.x, fmaf(w2, v.y, bb)));
        o.y = fmaf(w0, v.x, fmaf(w1, v.y, fmaf(w2, v.z, bb)));
        o.z = fmaf(w0, v.y, fmaf(w1, v.z, fmaf(w2, v.w, bb)));
        o.w = fmaf(w0, v.z, fmaf(w1, v.w, fmaf(w2, r,   bb)));
        ot[p] = o;
    }
}

extern "C" void kernel_launch(void* const* d_in, const int* in_sizes, int n_in,
                              void* d_out, int out_size)
{
    const float* x    = (const float*)d_in[0];
    const float* w    = (const float*)d_in[1];
    const float* bias = (const float*)d_in[2];
    float* out        = (float*)d_out;

    dwconv1d_kernel<<<NBLOCKS, NTHREADS>>>(x, w, bias, out);
}